// round 17
// baseline (speedup 1.0000x reference)
#include <cuda_runtime.h>
#include <cuda_fp16.h>
#include <math.h>

#define H      1024
#define TSTEPS 2048
#define KOUT   64
#define NBLK   128     // = H/8, one block per 8 hidden units
#define NTHR   512     // 16 warps -> 32 gate rows (2 rows per warp)

// Scratch (device globals: no allocation allowed in kernel_launch)
__device__ float g_hs[TSTEPS * H];   // h_t history (consumed by the MLP pass)
// Broadcast ping-pong: 2 slots x 512 u64 packets {tag:32 | h1:fp16 | h0:fp16}.
// ONE single-copy-atomic 8B word now carries both h values AND the tag --
// strictly stronger than the R9/R16 two-packet scheme, half the poll traffic
// (4KB/block/generation). STRONG (relaxed.gpu) ops only; NO fences in the hot
// loop (R12: gpu-scope fences emit CCTL.IVALL L1-flushes, 4x loss).
// tag = step+1: zero-init never matches; cross-replay residue is benign.
__device__ __align__(16) unsigned long long g_bc64[2 * 512];

// ---------- helpers ----------

__device__ __forceinline__ float2 ffma2(float2 a, float2 b, float2 c) {
    unsigned long long ua = *reinterpret_cast<unsigned long long*>(&a);
    unsigned long long ub = *reinterpret_cast<unsigned long long*>(&b);
    unsigned long long uc = *reinterpret_cast<unsigned long long*>(&c);
    unsigned long long ud;
    asm("fma.rn.f32x2 %0, %1, %2, %3;" : "=l"(ud) : "l"(ua), "l"(ub), "l"(uc));
    return *reinterpret_cast<float2*>(&ud);
}

__device__ __forceinline__ unsigned long long ld_relaxed_u64(const unsigned long long* p) {
    unsigned long long v;
    asm volatile("ld.relaxed.gpu.global.u64 %0, [%1];" : "=l"(v) : "l"(p) : "memory");
    return v;
}

__device__ __forceinline__ void st_relaxed_u64(unsigned long long* p, unsigned long long v) {
    asm volatile("st.relaxed.gpu.global.u64 [%0], %1;" :: "l"(p), "l"(v) : "memory");
}

// ---------- persistent LSTM recurrence (R16 layout, fp16-packed transport) ----
//
// Block b owns hidden units [8b, 8b+8). Warp w (0..15) computes gate rows
// r0=2w, r1=2w+1 (local); global row R = (r>>3)*H + b*8 + (r&7); order i,f,g,o.
// Weights Wc = Wih+Whh in registers (2 rows x 8 float4/thread -- the proven
// register sweet spot; 4 rows/thread spills, column-split regresses).
// Transport: thread tid polls ONE u64 packet (tag + 2 fp16 h values) with a
// single relaxed load per spin -- minimum possible poll traffic. fp16
// rounding of the transported h injects ~5e-4/step; the recurrence is
// strongly contractive (R10: 1e-6/op -> 2e-7 final), predicted final ~1e-4.

__global__ void __launch_bounds__(NTHR, 1)
lstm_kernel(const float* __restrict__ z,
            const float* __restrict__ Wih,
            const float* __restrict__ Whh,
            const float* __restrict__ bih,
            const float* __restrict__ bhh)
{
    __shared__ __align__(16) float h_sm[H];
    __shared__ float gates_sm[32];

    const int tid = threadIdx.x;
    const int b   = blockIdx.x;
    const int w   = tid >> 5;
    const int l   = tid & 31;
    const int r0  = 2 * w;
    const int r1  = 2 * w + 1;
    const int R0  = (r0 >> 3) * H + b * 8 + (r0 & 7);
    const int R1  = (r1 >> 3) * H + b * 8 + (r1 & 7);

    // Stage z into h_sm (input of step 0).
    reinterpret_cast<float2*>(h_sm)[tid] = reinterpret_cast<const float2*>(z)[tid];
    __syncthreads();

    const float4* Wih4 = reinterpret_cast<const float4*>(Wih);
    const float4* Whh4 = reinterpret_cast<const float4*>(Whh);
    const float4* h4   = reinterpret_cast<const float4*>(h_sm);

    // Prologue: load Wih/Whh once; compute step-0 partials with Wih (h0=0),
    // keep Wc = Wih + Whh resident in registers for all later steps.
    float4 wc0[8], wc1[8];
    float2 a0 = make_float2(0.f, 0.f);
    float2 a1 = make_float2(0.f, 0.f);
#pragma unroll
    for (int i = 0; i < 8; i++) {
        const int c0i = R0 * (H / 4) + i * 32 + l;
        const int c1i = R1 * (H / 4) + i * 32 + l;
        float4 wi0 = Wih4[c0i], wh0 = Whh4[c0i];
        float4 wi1 = Wih4[c1i], wh1 = Whh4[c1i];
        float4 hv  = h4[i * 32 + l];
        a0 = ffma2(make_float2(wi0.x, wi0.y), make_float2(hv.x, hv.y), a0);
        a0 = ffma2(make_float2(wi0.z, wi0.w), make_float2(hv.z, hv.w), a0);
        a1 = ffma2(make_float2(wi1.x, wi1.y), make_float2(hv.x, hv.y), a1);
        a1 = ffma2(make_float2(wi1.z, wi1.w), make_float2(hv.z, hv.w), a1);
        wc0[i] = make_float4(wi0.x + wh0.x, wi0.y + wh0.y, wi0.z + wh0.z, wi0.w + wh0.w);
        wc1[i] = make_float4(wi1.x + wh1.x, wi1.y + wh1.y, wi1.z + wh1.z, wi1.w + wh1.w);
    }
    const float bc0 = bih[R0] + bhh[R0];
    const float bc1 = bih[R1] + bhh[R1];

    float c = 0.0f;   // cell state: live only in warp 0, lanes 0..7

    for (int t = 0; t < TSTEPS; t++) {
        if (t > 0) {
            // Poll own packet of h_{t-1}: ONE 8B strong load per spin
            // iteration; tag + both fp16 h values in a single atomic word.
            const unsigned want = (unsigned)t;            // tag of step t-1
            const unsigned long long* s = g_bc64 + ((t - 1) & 1) * 512 + tid;
            unsigned long long p;
            do {
                p = ld_relaxed_u64(s);
            } while ((unsigned)(p >> 32) != want);
            __half2 hh = *reinterpret_cast<__half2*>(&p);   // low 32 bits
            reinterpret_cast<float2*>(h_sm)[tid] = __half22float2(hh);
            __syncthreads();

            // Matvec: gates = Wc @ h (register weights, smem h, packed f32x2 FMA)
            a0 = make_float2(0.f, 0.f);
            a1 = make_float2(0.f, 0.f);
#pragma unroll
            for (int i = 0; i < 8; i++) {
                float4 hv = h4[i * 32 + l];
                a0 = ffma2(make_float2(wc0[i].x, wc0[i].y), make_float2(hv.x, hv.y), a0);
                a0 = ffma2(make_float2(wc0[i].z, wc0[i].w), make_float2(hv.z, hv.w), a0);
                a1 = ffma2(make_float2(wc1[i].x, wc1[i].y), make_float2(hv.x, hv.y), a1);
                a1 = ffma2(make_float2(wc1[i].z, wc1[i].w), make_float2(hv.z, hv.w), a1);
            }
        }

        // Warp reductions: two interleaved 5-level butterflies.
        float s0 = a0.x + a0.y;
        float s1 = a1.x + a1.y;
#pragma unroll
        for (int d = 16; d > 0; d >>= 1) {
            s0 += __shfl_xor_sync(0xffffffffu, s0, d);
            s1 += __shfl_xor_sync(0xffffffffu, s1, d);
        }
        if (l == 0) {
            gates_sm[r0] = s0 + bc0;
            gates_sm[r1] = s1 + bc1;
        }
        __syncthreads();

        // Gate combine: warp 0, one gate per lane; UNIFORM nonlinearity path
        // (tanh(x) = 2*sigmoid(2x)-1) -> single expf sequence, no divergence.
        if (w == 0) {
            float gval = gates_sm[l];
            const bool is_g = (l >= 16 && l < 24);     // tanh lanes
            float xin = is_g ? 2.0f * gval : gval;
            float sg  = 1.0f / (1.0f + expf(-xin));
            float nl  = is_g ? fmaf(2.0f, sg, -1.0f) : sg;
            const int k = l & 7;
            float gi = __shfl_sync(0xffffffffu, nl, k);
            float gf = __shfl_sync(0xffffffffu, nl, 8 + k);
            float gg = __shfl_sync(0xffffffffu, nl, 16 + k);
            float go = __shfl_sync(0xffffffffu, nl, 24 + k);
            if (l < 8) {
                c = gf * c + gi * gg;
                float h = go * tanhf(c);

                // Pack pairs: lane j<4 publishes {tag | fp16(h[2j+1]) | fp16(h[2j])}.
                float hlo = __shfl_sync(0xffu, h, (2 * l) & 7);
                float hhi = __shfl_sync(0xffu, h, (2 * l + 1) & 7);
                if (l < 4) {
                    __half2 hh = __floats2half2_rn(hlo, hhi);
                    unsigned long long pkt =
                        ((unsigned long long)(unsigned)(t + 1) << 32) |
                        (unsigned long long)*reinterpret_cast<unsigned*>(&hh);
                    st_relaxed_u64(g_bc64 + (t & 1) * 512 + b * 4 + l, pkt);
                }
                g_hs[(size_t)t * H + b * 8 + l] = h;   // history for MLP (fp32)
            }
        }
        // Hold all warps until the local publish is issued: prevents 15 warps
        // from flooding L2 with stale polls while producers commit stores.
        __syncthreads();
    }
}

// ---------- per-timestep MLP head (R1's proven version) ----------

__global__ void __launch_bounds__(128)
mlp_kernel(const float* __restrict__ W1, const float* __restrict__ b1,
           const float* __restrict__ W2, const float* __restrict__ b2,
           const float* __restrict__ W3, const float* __restrict__ b3,
           float* __restrict__ out)
{
    __shared__ __align__(16) float h_sm[H];
    __shared__ float a1s[32];
    __shared__ float a2s[32];

    const int t   = blockIdx.x;
    const int tid = threadIdx.x;
    const int w   = tid >> 5;
    const int l   = tid & 31;

    const float4* src = reinterpret_cast<const float4*>(g_hs + (size_t)t * H);
    reinterpret_cast<float4*>(h_sm)[tid]       = src[tid];
    reinterpret_cast<float4*>(h_sm)[128 + tid] = src[128 + tid];
    __syncthreads();

    // Layer 1: 32 outputs; warp w computes outputs [8w, 8w+8), lanes stride columns.
    float acc[8];
#pragma unroll
    for (int oo = 0; oo < 8; oo++) acc[oo] = 0.0f;
#pragma unroll 4
    for (int i = 0; i < 32; i++) {
        float hv = h_sm[i * 32 + l];
#pragma unroll
        for (int oo = 0; oo < 8; oo++) {
            acc[oo] = fmaf(W1[(w * 8 + oo) * H + i * 32 + l], hv, acc[oo]);
        }
    }
#pragma unroll
    for (int oo = 0; oo < 8; oo++) {
#pragma unroll
        for (int d = 16; d > 0; d >>= 1)
            acc[oo] += __shfl_xor_sync(0xffffffffu, acc[oo], d);
    }
    if (l == 0) {
#pragma unroll
        for (int oo = 0; oo < 8; oo++) {
            int o = w * 8 + oo;
            a1s[o] = fmaxf(acc[oo] + b1[o], 0.0f);
        }
    }
    __syncthreads();

    // Layer 2: 32x32
    if (tid < 32) {
        float a = b2[tid];
#pragma unroll
        for (int k = 0; k < 32; k++) a = fmaf(W2[tid * 32 + k], a1s[k], a);
        a2s[tid] = fmaxf(a, 0.0f);
    }
    __syncthreads();

    // Layer 3: 64x32 -> output
    if (tid < KOUT) {
        float a = b3[tid];
#pragma unroll
        for (int k = 0; k < 32; k++) a = fmaf(W3[tid * 32 + k], a2s[k], a);
        out[(size_t)t * KOUT + tid] = a;
    }
}

// ---------- launch ----------

extern "C" void kernel_launch(void* const* d_in, const int* in_sizes, int n_in,
                              void* d_out, int out_size)
{
    const float* z   = (const float*)d_in[0];
    const float* Wih = (const float*)d_in[1];
    const float* Whh = (const float*)d_in[2];
    const float* bih = (const float*)d_in[3];
    const float* bhh = (const float*)d_in[4];
    const float* W1  = (const float*)d_in[5];
    const float* b1  = (const float*)d_in[6];
    const float* W2  = (const float*)d_in[7];
    const float* b2  = (const float*)d_in[8];
    const float* W3  = (const float*)d_in[9];
    const float* b3  = (const float*)d_in[10];
    float* out = (float*)d_out;

    lstm_kernel<<<NBLK, NTHR>>>(z, Wih, Whh, bih, bhh);
    mlp_kernel<<<TSTEPS, 128>>>(W1, b1, W2, b2, W3, b3, out);
}